// round 5
// baseline (speedup 1.0000x reference)
#include <cuda_runtime.h>
#include <math.h>

#define NN  100000
#define EE  3200000
#define DIM 32
#define FIN 128
#define NC  10
#define CAP 128            // bucket capacity per node (Poisson(32) -> safe)

#define GT   782           // gemm tiles: ceil(NN/128)
#define EVB  1024          // even-block count in fused kernel (grid = 2048)
#define SCW  (EVB * 256)   // scatter worker threads (odd blocks)
#define FCB  (EVB - GT)    // fcx blocks (even blocks beyond gemm tiles)

// ---------------- scratch (static device globals; no allocations) ----------------
// g_HN has one extra row (index NN) that is NEVER written: device globals are
// zero-initialized, so it is a permanent all-zero row used as a branchless
// dummy target for inactive edge slots in the aggregation kernel.
__device__ __align__(256) float g_HN[(NN + 1) * DIM];
__device__ __align__(256) float g_SB[NN * DIM];
__device__ __align__(256) float g_H1[NN * DIM];
__device__ __align__(256) float g_H2[NN * DIM];
__device__ __align__(256) float g_H3[NN * DIM];
__device__ __align__(256) float g_fcp[NN * NC];    // partial logits (x-part + bias)
__device__ int g_cnt[NN];                          // zero at start & end of every call
__device__ int g_bucket[NN * CAP];

// =================================================================================
// Fused kernel: role per block.
//   odd  blocks             : edge scatter into buckets (atomic counts)
//   even blocks, t <  GT    : dual GEMM tile (x@Wn0 -> HN, x@Ws0+bn0 -> SB), DIN=128
//   even blocks, t >= GT    : partial FC (x @ fc_w[0:128] + fc_b -> g_fcp)
// =================================================================================
__global__ void fused0_kernel(const float* __restrict__ x,
                              const float* __restrict__ Wn,
                              const float* __restrict__ bn,
                              const float* __restrict__ Ws,
                              const int*   __restrict__ src,
                              const int*   __restrict__ dst,
                              const float* __restrict__ fcw,
                              const float* __restrict__ fcb) {
    extern __shared__ float sm[];
    int bid = blockIdx.x;
    int tid = threadIdx.x;

    if (bid & 1) {
        // -------- scatter role --------
        int wid = (bid >> 1) * 256 + tid;
        const int step = SCW;
        int e = wid;
        for (; e + 3 * step < EE; e += 4 * step) {
            int d0 = dst[e];            int s0 = src[e];
            int d1 = dst[e + step];     int s1 = src[e + step];
            int d2 = dst[e + 2 * step]; int s2 = src[e + 2 * step];
            int d3 = dst[e + 3 * step]; int s3 = src[e + 3 * step];
            int p0 = atomicAdd(&g_cnt[d0], 1);
            int p1 = atomicAdd(&g_cnt[d1], 1);
            int p2 = atomicAdd(&g_cnt[d2], 1);
            int p3 = atomicAdd(&g_cnt[d3], 1);
            if (p0 < CAP) g_bucket[d0 * CAP + p0] = s0;
            if (p1 < CAP) g_bucket[d1 * CAP + p1] = s1;
            if (p2 < CAP) g_bucket[d2 * CAP + p2] = s2;
            if (p3 < CAP) g_bucket[d3 * CAP + p3] = s3;
        }
        for (; e < EE; e += step) {
            int d = dst[e];
            int p = atomicAdd(&g_cnt[d], 1);
            if (p < CAP) g_bucket[d * CAP + p] = src[e];
        }
        return;
    }

    int t = bid >> 1;
    if (t < GT) {
        // -------- dual GEMM role (DIN=128, k-chunked by 32) --------
        float* sX  = sm;                 // 128 * 33
        float* sWn = sX + 128 * 33;      // 128 * 32
        float* sWs = sWn + 128 * 32;     // 128 * 32
        float* sb  = sWs + 128 * 32;     // 32

        for (int i = tid; i < 128 * 32; i += 256) { sWn[i] = Wn[i]; sWs[i] = Ws[i]; }
        if (tid < 32) sb[tid] = bn[tid];

        int n0 = t * 128;
        int g_c = tid & 7;
        int g_n = tid >> 3;

        float hn[4][4], ss[4][4];
#pragma unroll
        for (int i = 0; i < 4; i++)
#pragma unroll
            for (int j = 0; j < 4; j++) { hn[i][j] = 0.f; ss[i][j] = 0.f; }

        for (int kc = 0; kc < 4; ++kc) {
            // stage 128 nodes x 32 k of x
            for (int i = tid; i < 1024; i += 256) {   // i indexes float4
                int node = i >> 3;
                int k4   = (i & 7) * 4;
                float4 v = make_float4(0.f, 0.f, 0.f, 0.f);
                if (n0 + node < NN)
                    v = *reinterpret_cast<const float4*>(
                        x + (size_t)(n0 + node) * FIN + kc * 32 + k4);
                float* p = &sX[node * 33 + k4];
                p[0] = v.x; p[1] = v.y; p[2] = v.z; p[3] = v.w;
            }
            __syncthreads();
#pragma unroll 8
            for (int kk = 0; kk < 32; ++kk) {
                int k = kc * 32 + kk;
                float4 wn = *reinterpret_cast<const float4*>(&sWn[k * 32 + g_c * 4]);
                float4 ws = *reinterpret_cast<const float4*>(&sWs[k * 32 + g_c * 4]);
#pragma unroll
                for (int i = 0; i < 4; ++i) {
                    float xv = sX[(g_n * 4 + i) * 33 + kk];
                    hn[i][0] = fmaf(xv, wn.x, hn[i][0]);
                    hn[i][1] = fmaf(xv, wn.y, hn[i][1]);
                    hn[i][2] = fmaf(xv, wn.z, hn[i][2]);
                    hn[i][3] = fmaf(xv, wn.w, hn[i][3]);
                    ss[i][0] = fmaf(xv, ws.x, ss[i][0]);
                    ss[i][1] = fmaf(xv, ws.y, ss[i][1]);
                    ss[i][2] = fmaf(xv, ws.z, ss[i][2]);
                    ss[i][3] = fmaf(xv, ws.w, ss[i][3]);
                }
            }
            __syncthreads();
        }

        float4 bb = *reinterpret_cast<const float4*>(&sb[g_c * 4]);
#pragma unroll
        for (int i = 0; i < 4; ++i) {
            int node = n0 + g_n * 4 + i;
            if (node < NN) {
                reinterpret_cast<float4*>(g_HN + (size_t)node * DIM)[g_c] =
                    make_float4(hn[i][0], hn[i][1], hn[i][2], hn[i][3]);
                reinterpret_cast<float4*>(g_SB + (size_t)node * DIM)[g_c] =
                    make_float4(ss[i][0] + bb.x, ss[i][1] + bb.y,
                                ss[i][2] + bb.z, ss[i][3] + bb.w);
            }
        }
        return;
    }

    // -------- partial FC role: g_fcp = x @ fc_w[0:128,:] + fc_b --------
    {
        float* sW = sm;                              // 128 * 10
        for (int i = tid; i < FIN * NC; i += 256) sW[i] = fcw[i];
        __syncthreads();
        float b[NC];
#pragma unroll
        for (int c = 0; c < NC; c++) b[c] = __ldg(&fcb[c]);

        int wid = (t - GT) * 256 + tid;
        const int nth = FCB * 256;
        for (int n = wid; n < NN; n += nth) {
            float acc[NC];
#pragma unroll
            for (int c = 0; c < NC; c++) acc[c] = b[c];
            const float* xr = x + (size_t)n * FIN;
#pragma unroll 4
            for (int k = 0; k < FIN; ++k) {
                float v = __ldg(&xr[k]);
                const float* w = &sW[k * NC];
#pragma unroll
                for (int c = 0; c < NC; c++) acc[c] = fmaf(v, w[c], acc[c]);
            }
            float* o = g_fcp + (size_t)n * NC;
#pragma unroll
            for (int c = 0; c < NC; c++) o[c] = acc[c];
        }
    }
}

// ---------------- dual GEMM for DIM->DIM layers (DIN=32) ----------------
__global__ void gemm_dual32_kernel(const float* __restrict__ X,
                                   const float* __restrict__ Wn,
                                   const float* __restrict__ bn,
                                   const float* __restrict__ Ws) {
    __shared__ float sX[128 * 33];
    __shared__ float sWn[32 * 32];
    __shared__ float sWs[32 * 32];
    __shared__ float sb[32];

    int tid = threadIdx.x;
    for (int i = tid; i < 32 * 32; i += 256) { sWn[i] = Wn[i]; sWs[i] = Ws[i]; }
    if (tid < 32) sb[tid] = bn[tid];

    int n0 = blockIdx.x * 128;
    for (int i = tid; i < 1024; i += 256) {   // float4 index: 128 nodes * 8 vec
        int node = i >> 3;
        int k4   = (i & 7) * 4;
        float4 v = make_float4(0.f, 0.f, 0.f, 0.f);
        if (n0 + node < NN)
            v = *reinterpret_cast<const float4*>(X + (size_t)(n0 + node) * DIM + k4);
        float* p = &sX[node * 33 + k4];
        p[0] = v.x; p[1] = v.y; p[2] = v.z; p[3] = v.w;
    }
    __syncthreads();

    int g_c = tid & 7;
    int g_n = tid >> 3;

    float hn[4][4], ss[4][4];
#pragma unroll
    for (int i = 0; i < 4; i++)
#pragma unroll
        for (int j = 0; j < 4; j++) { hn[i][j] = 0.f; ss[i][j] = 0.f; }

#pragma unroll 8
    for (int k = 0; k < 32; ++k) {
        float4 wn = *reinterpret_cast<const float4*>(&sWn[k * 32 + g_c * 4]);
        float4 ws = *reinterpret_cast<const float4*>(&sWs[k * 32 + g_c * 4]);
#pragma unroll
        for (int i = 0; i < 4; ++i) {
            float xv = sX[(g_n * 4 + i) * 33 + k];
            hn[i][0] = fmaf(xv, wn.x, hn[i][0]);
            hn[i][1] = fmaf(xv, wn.y, hn[i][1]);
            hn[i][2] = fmaf(xv, wn.z, hn[i][2]);
            hn[i][3] = fmaf(xv, wn.w, hn[i][3]);
            ss[i][0] = fmaf(xv, ws.x, ss[i][0]);
            ss[i][1] = fmaf(xv, ws.y, ss[i][1]);
            ss[i][2] = fmaf(xv, ws.z, ss[i][2]);
            ss[i][3] = fmaf(xv, ws.w, ss[i][3]);
        }
    }

    float4 bb = *reinterpret_cast<const float4*>(&sb[g_c * 4]);
#pragma unroll
    for (int i = 0; i < 4; ++i) {
        int node = n0 + g_n * 4 + i;
        if (node < NN) {
            reinterpret_cast<float4*>(g_HN + (size_t)node * DIM)[g_c] =
                make_float4(hn[i][0], hn[i][1], hn[i][2], hn[i][3]);
            reinterpret_cast<float4*>(g_SB + (size_t)node * DIM)[g_c] =
                make_float4(ss[i][0] + bb.x, ss[i][1] + bb.y,
                            ss[i][2] + bb.z, ss[i][3] + bb.w);
        }
    }
}

// ---------------- bucket aggregation + relu (vectorized, fixed-trip unroll) ------
// one warp per node; lane = (edge_group:2, feature_quad:3).
// Each 32-edge chunk is processed by a fully-unrolled 8-iteration loop (4 edges
// per iteration); inactive slots are redirected (branchless) to the permanent
// zero row g_HN[NN]. Constant trip count -> ptxas front-batches 8 independent
// LDG.128 per lane (MLP=8), hiding L2 latency.
__global__ void aggregate_relu_kernel(float* __restrict__ OUT, int zero_flag) {
    int node = (blockIdx.x * blockDim.x + threadIdx.x) >> 5;
    int lane = threadIdx.x & 31;
    if (node >= NN) return;

    int fq = (lane & 7) * 4;      // feature quad offset within the 32-dim row
    int eg = lane >> 3;           // edge group 0..3

    int cnt = g_cnt[node];
    int m = min(cnt, CAP);
    const int* bkt = &g_bucket[(size_t)node * CAP];
    const float* hbase = g_HN + fq;     // loop-invariant; addr = hbase + s*DIM

    float4 a0 = make_float4(0.f, 0.f, 0.f, 0.f);
    float4 a1 = make_float4(0.f, 0.f, 0.f, 0.f);

    for (int base = 0; base < m; base += 32) {
        int nb = min(32, m - base);
        int idx = (lane < nb) ? bkt[base + lane] : NN;
#pragma unroll
        for (int j = 0; j < 32; j += 8) {
            int e0 = j + eg;
            int e1 = j + 4 + eg;
            int s0 = __shfl_sync(0xffffffffu, idx, e0);
            int s1 = __shfl_sync(0xffffffffu, idx, e1);
            s0 = (e0 < nb) ? s0 : NN;             // branchless: zero row
            s1 = (e1 < nb) ? s1 : NN;
            float4 v0 = *reinterpret_cast<const float4*>(hbase + (size_t)s0 * DIM);
            float4 v1 = *reinterpret_cast<const float4*>(hbase + (size_t)s1 * DIM);
            a0.x += v0.x; a0.y += v0.y; a0.z += v0.z; a0.w += v0.w;
            a1.x += v1.x; a1.y += v1.y; a1.z += v1.z; a1.w += v1.w;
        }
    }

    float4 acc;
    acc.x = a0.x + a1.x; acc.y = a0.y + a1.y;
    acc.z = a0.z + a1.z; acc.w = a0.w + a1.w;

    // reduce across the 4 edge groups (lanes l, l+8, l+16, l+24)
    acc.x += __shfl_xor_sync(0xffffffffu, acc.x, 8);
    acc.y += __shfl_xor_sync(0xffffffffu, acc.y, 8);
    acc.z += __shfl_xor_sync(0xffffffffu, acc.z, 8);
    acc.w += __shfl_xor_sync(0xffffffffu, acc.w, 8);
    acc.x += __shfl_xor_sync(0xffffffffu, acc.x, 16);
    acc.y += __shfl_xor_sync(0xffffffffu, acc.y, 16);
    acc.z += __shfl_xor_sync(0xffffffffu, acc.z, 16);
    acc.w += __shfl_xor_sync(0xffffffffu, acc.w, 16);

    if (eg == 0) {
        float4 sb = *reinterpret_cast<const float4*>(&g_SB[(size_t)node * DIM + fq]);
        float4 o;
        o.x = fmaxf(acc.x + sb.x, 0.f);
        o.y = fmaxf(acc.y + sb.y, 0.f);
        o.z = fmaxf(acc.z + sb.z, 0.f);
        o.w = fmaxf(acc.w + sb.w, 0.f);
        *reinterpret_cast<float4*>(&OUT[(size_t)node * DIM + fq]) = o;
        if (zero_flag && lane == 0) g_cnt[node] = 0;   // restore invariant
    }
}

// ---------------- final FC (H-part) + log_softmax ----------------
__global__ void fc_final_kernel(const float* __restrict__ W,   // full fc_w [224,10]
                                float* __restrict__ OUT) {
    __shared__ float sW[3 * DIM * NC];   // rows 128..223
    for (int i = threadIdx.x; i < 3 * DIM * NC; i += blockDim.x)
        sW[i] = W[FIN * NC + i];
    __syncthreads();

    int n = blockIdx.x * blockDim.x + threadIdx.x;
    if (n >= NN) return;

    float acc[NC];
    const float* p = g_fcp + (size_t)n * NC;
#pragma unroll
    for (int c = 0; c < NC; c++) acc[c] = p[c];

    const float* h1 = g_H1 + (size_t)n * DIM;
    const float* h2 = g_H2 + (size_t)n * DIM;
    const float* h3 = g_H3 + (size_t)n * DIM;
#pragma unroll 4
    for (int k = 0; k < DIM; ++k) {
        float v = h1[k];
        const float* w = &sW[k * NC];
#pragma unroll
        for (int c = 0; c < NC; c++) acc[c] = fmaf(v, w[c], acc[c]);
    }
#pragma unroll 4
    for (int k = 0; k < DIM; ++k) {
        float v = h2[k];
        const float* w = &sW[(DIM + k) * NC];
#pragma unroll
        for (int c = 0; c < NC; c++) acc[c] = fmaf(v, w[c], acc[c]);
    }
#pragma unroll 4
    for (int k = 0; k < DIM; ++k) {
        float v = h3[k];
        const float* w = &sW[(2 * DIM + k) * NC];
#pragma unroll
        for (int c = 0; c < NC; c++) acc[c] = fmaf(v, w[c], acc[c]);
    }

    float mx = acc[0];
#pragma unroll
    for (int c = 1; c < NC; c++) mx = fmaxf(mx, acc[c]);
    float s = 0.f;
#pragma unroll
    for (int c = 0; c < NC; c++) s += expf(acc[c] - mx);
    float l = logf(s);
    float* o = OUT + (size_t)n * NC;
#pragma unroll
    for (int c = 0; c < NC; c++) o[c] = acc[c] - mx - l;
}

// ---------------- launch ----------------
extern "C" void kernel_launch(void* const* d_in, const int* in_sizes, int n_in,
                              void* d_out, int out_size) {
    const float* x   = (const float*)d_in[0];
    const int*   src = (const int*)d_in[1];
    const int*   dst = (const int*)d_in[2];
    const float* Wn0 = (const float*)d_in[3];
    const float* bn0 = (const float*)d_in[4];
    const float* Ws0 = (const float*)d_in[5];
    const float* Wn1 = (const float*)d_in[6];
    const float* bn1 = (const float*)d_in[7];
    const float* Ws1 = (const float*)d_in[8];
    const float* Wn2 = (const float*)d_in[9];
    const float* bn2 = (const float*)d_in[10];
    const float* Ws2 = (const float*)d_in[11];
    const float* fcw = (const float*)d_in[12];
    const float* fcb = (const float*)d_in[13];
    float* out = (float*)d_out;

    float *H1, *H2, *H3;
    cudaGetSymbolAddress((void**)&H1, g_H1);
    cudaGetSymbolAddress((void**)&H2, g_H2);
    cudaGetSymbolAddress((void**)&H3, g_H3);

    constexpr int SMEMF = (128 * 33 + 2 * 128 * 32 + 32) * 4;   // 49792 B
    cudaFuncSetAttribute(fused0_kernel,
                         cudaFuncAttributeMaxDynamicSharedMemorySize, SMEMF);

    const int ablocks = (NN * 32 + 255) / 256;

    // layer 0 GEMM + edge scatter + partial FC, all overlapped in one launch
    fused0_kernel<<<2 * EVB, 256, SMEMF>>>(x, Wn0, bn0, Ws0, src, dst, fcw, fcb);
    aggregate_relu_kernel<<<ablocks, 256>>>(H1, 0);
    // layer 1
    gemm_dual32_kernel<<<GT, 256>>>(H1, Wn1, bn1, Ws1);
    aggregate_relu_kernel<<<ablocks, 256>>>(H2, 0);
    // layer 2
    gemm_dual32_kernel<<<GT, 256>>>(H2, Wn2, bn2, Ws2);
    aggregate_relu_kernel<<<ablocks, 256>>>(H3, 1);   // zeroes g_cnt after last use
    // readout (x-part already in g_fcp)
    fc_final_kernel<<<(NN + 255) / 256, 256>>>(fcw, out);
}

// round 8
// speedup vs baseline: 1.6316x; 1.6316x over previous
#include <cuda_runtime.h>
#include <cuda_fp16.h>
#include <math.h>

#define NN  100000
#define EE  3200000
#define DIM 32
#define FIN 128
#define NC  10
#define CAP 128            // bucket capacity per node (Poisson(32) -> safe)

#define GT   782           // gemm tiles: ceil(NN/128)
#define EVB  1024          // even-block count in fused kernel (grid = 2048)
#define SCW  (EVB * 256)   // scatter worker threads (odd blocks)
#define FCB  (EVB - GT)    // fcx blocks (even blocks beyond gemm tiles)

// ---------------- scratch (static device globals; no allocations) ----------------
// g_HNh holds neighbor messages in fp16 (row = 32 halves = 64 B). It has one
// extra row (index NN) that is NEVER written: device globals are
// zero-initialized, so it is a permanent all-zero row used as a branchless
// dummy target for inactive edge slots in the aggregation kernel.
__device__ __align__(256) __half g_HNh[(NN + 1) * DIM];
__device__ __align__(256) float g_SB[NN * DIM];
__device__ __align__(256) float g_H1[NN * DIM];
__device__ __align__(256) float g_H2[NN * DIM];
__device__ __align__(256) float g_H3[NN * DIM];
__device__ __align__(256) float g_fcp[NN * NC];    // partial logits (x-part + bias)
__device__ int g_cnt[NN];                          // zero at start & end of every call
__device__ int g_bucket[NN * CAP];

// =================================================================================
// Fused kernel: role per block.
//   odd  blocks             : edge scatter into buckets (atomic counts)
//   even blocks, t <  GT    : dual GEMM tile (x@Wn0 -> HNh, x@Ws0+bn0 -> SB), DIN=128
//   even blocks, t >= GT    : partial FC (x @ fc_w[0:128] + fc_b -> g_fcp)
// =================================================================================
__global__ void fused0_kernel(const float* __restrict__ x,
                              const float* __restrict__ Wn,
                              const float* __restrict__ bn,
                              const float* __restrict__ Ws,
                              const int*   __restrict__ src,
                              const int*   __restrict__ dst,
                              const float* __restrict__ fcw,
                              const float* __restrict__ fcb) {
    extern __shared__ float sm[];
    int bid = blockIdx.x;
    int tid = threadIdx.x;

    if (bid & 1) {
        // -------- scatter role --------
        int wid = (bid >> 1) * 256 + tid;
        const int step = SCW;
        int e = wid;
        for (; e + 3 * step < EE; e += 4 * step) {
            int d0 = dst[e];            int s0 = src[e];
            int d1 = dst[e + step];     int s1 = src[e + step];
            int d2 = dst[e + 2 * step]; int s2 = src[e + 2 * step];
            int d3 = dst[e + 3 * step]; int s3 = src[e + 3 * step];
            int p0 = atomicAdd(&g_cnt[d0], 1);
            int p1 = atomicAdd(&g_cnt[d1], 1);
            int p2 = atomicAdd(&g_cnt[d2], 1);
            int p3 = atomicAdd(&g_cnt[d3], 1);
            if (p0 < CAP) g_bucket[d0 * CAP + p0] = s0;
            if (p1 < CAP) g_bucket[d1 * CAP + p1] = s1;
            if (p2 < CAP) g_bucket[d2 * CAP + p2] = s2;
            if (p3 < CAP) g_bucket[d3 * CAP + p3] = s3;
        }
        for (; e < EE; e += step) {
            int d = dst[e];
            int p = atomicAdd(&g_cnt[d], 1);
            if (p < CAP) g_bucket[d * CAP + p] = src[e];
        }
        return;
    }

    int t = bid >> 1;
    if (t < GT) {
        // -------- dual GEMM role (DIN=128, k-chunked by 32) --------
        float* sX  = sm;                 // 128 * 33
        float* sWn = sX + 128 * 33;      // 128 * 32
        float* sWs = sWn + 128 * 32;     // 128 * 32
        float* sb  = sWs + 128 * 32;     // 32

        for (int i = tid; i < 128 * 32; i += 256) { sWn[i] = Wn[i]; sWs[i] = Ws[i]; }
        if (tid < 32) sb[tid] = bn[tid];

        int n0 = t * 128;
        int g_c = tid & 7;
        int g_n = tid >> 3;

        float hn[4][4], ss[4][4];
#pragma unroll
        for (int i = 0; i < 4; i++)
#pragma unroll
            for (int j = 0; j < 4; j++) { hn[i][j] = 0.f; ss[i][j] = 0.f; }

        for (int kc = 0; kc < 4; ++kc) {
            // stage 128 nodes x 32 k of x
            for (int i = tid; i < 1024; i += 256) {   // i indexes float4
                int node = i >> 3;
                int k4   = (i & 7) * 4;
                float4 v = make_float4(0.f, 0.f, 0.f, 0.f);
                if (n0 + node < NN)
                    v = *reinterpret_cast<const float4*>(
                        x + (size_t)(n0 + node) * FIN + kc * 32 + k4);
                float* p = &sX[node * 33 + k4];
                p[0] = v.x; p[1] = v.y; p[2] = v.z; p[3] = v.w;
            }
            __syncthreads();
#pragma unroll 8
            for (int kk = 0; kk < 32; ++kk) {
                int k = kc * 32 + kk;
                float4 wn = *reinterpret_cast<const float4*>(&sWn[k * 32 + g_c * 4]);
                float4 ws = *reinterpret_cast<const float4*>(&sWs[k * 32 + g_c * 4]);
#pragma unroll
                for (int i = 0; i < 4; ++i) {
                    float xv = sX[(g_n * 4 + i) * 33 + kk];
                    hn[i][0] = fmaf(xv, wn.x, hn[i][0]);
                    hn[i][1] = fmaf(xv, wn.y, hn[i][1]);
                    hn[i][2] = fmaf(xv, wn.z, hn[i][2]);
                    hn[i][3] = fmaf(xv, wn.w, hn[i][3]);
                    ss[i][0] = fmaf(xv, ws.x, ss[i][0]);
                    ss[i][1] = fmaf(xv, ws.y, ss[i][1]);
                    ss[i][2] = fmaf(xv, ws.z, ss[i][2]);
                    ss[i][3] = fmaf(xv, ws.w, ss[i][3]);
                }
            }
            __syncthreads();
        }

        float4 bb = *reinterpret_cast<const float4*>(&sb[g_c * 4]);
#pragma unroll
        for (int i = 0; i < 4; ++i) {
            int node = n0 + g_n * 4 + i;
            if (node < NN) {
                __half2 p0 = __floats2half2_rn(hn[i][0], hn[i][1]);
                __half2 p1 = __floats2half2_rn(hn[i][2], hn[i][3]);
                uint2 u = make_uint2(*reinterpret_cast<unsigned*>(&p0),
                                     *reinterpret_cast<unsigned*>(&p1));
                *(reinterpret_cast<uint2*>(g_HNh + (size_t)node * DIM) + g_c) = u;
                reinterpret_cast<float4*>(g_SB + (size_t)node * DIM)[g_c] =
                    make_float4(ss[i][0] + bb.x, ss[i][1] + bb.y,
                                ss[i][2] + bb.z, ss[i][3] + bb.w);
            }
        }
        return;
    }

    // -------- partial FC role: g_fcp = x @ fc_w[0:128,:] + fc_b --------
    {
        float* sW = sm;                              // 128 * 10
        for (int i = tid; i < FIN * NC; i += 256) sW[i] = fcw[i];
        __syncthreads();
        float b[NC];
#pragma unroll
        for (int c = 0; c < NC; c++) b[c] = __ldg(&fcb[c]);

        int wid = (t - GT) * 256 + tid;
        const int nth = FCB * 256;
        for (int n = wid; n < NN; n += nth) {
            float acc[NC];
#pragma unroll
            for (int c = 0; c < NC; c++) acc[c] = b[c];
            const float* xr = x + (size_t)n * FIN;
#pragma unroll 4
            for (int k = 0; k < FIN; ++k) {
                float v = __ldg(&xr[k]);
                const float* w = &sW[k * NC];
#pragma unroll
                for (int c = 0; c < NC; c++) acc[c] = fmaf(v, w[c], acc[c]);
            }
            float* o = g_fcp + (size_t)n * NC;
#pragma unroll
            for (int c = 0; c < NC; c++) o[c] = acc[c];
        }
    }
}

// ---------------- dual GEMM for DIM->DIM layers (DIN=32) ----------------
__global__ void gemm_dual32_kernel(const float* __restrict__ X,
                                   const float* __restrict__ Wn,
                                   const float* __restrict__ bn,
                                   const float* __restrict__ Ws) {
    __shared__ float sX[128 * 33];
    __shared__ float sWn[32 * 32];
    __shared__ float sWs[32 * 32];
    __shared__ float sb[32];

    int tid = threadIdx.x;
    for (int i = tid; i < 32 * 32; i += 256) { sWn[i] = Wn[i]; sWs[i] = Ws[i]; }
    if (tid < 32) sb[tid] = bn[tid];

    int n0 = blockIdx.x * 128;
    for (int i = tid; i < 1024; i += 256) {   // float4 index: 128 nodes * 8 vec
        int node = i >> 3;
        int k4   = (i & 7) * 4;
        float4 v = make_float4(0.f, 0.f, 0.f, 0.f);
        if (n0 + node < NN)
            v = *reinterpret_cast<const float4*>(X + (size_t)(n0 + node) * DIM + k4);
        float* p = &sX[node * 33 + k4];
        p[0] = v.x; p[1] = v.y; p[2] = v.z; p[3] = v.w;
    }
    __syncthreads();

    int g_c = tid & 7;
    int g_n = tid >> 3;

    float hn[4][4], ss[4][4];
#pragma unroll
    for (int i = 0; i < 4; i++)
#pragma unroll
        for (int j = 0; j < 4; j++) { hn[i][j] = 0.f; ss[i][j] = 0.f; }

#pragma unroll 8
    for (int k = 0; k < 32; ++k) {
        float4 wn = *reinterpret_cast<const float4*>(&sWn[k * 32 + g_c * 4]);
        float4 ws = *reinterpret_cast<const float4*>(&sWs[k * 32 + g_c * 4]);
#pragma unroll
        for (int i = 0; i < 4; ++i) {
            float xv = sX[(g_n * 4 + i) * 33 + k];
            hn[i][0] = fmaf(xv, wn.x, hn[i][0]);
            hn[i][1] = fmaf(xv, wn.y, hn[i][1]);
            hn[i][2] = fmaf(xv, wn.z, hn[i][2]);
            hn[i][3] = fmaf(xv, wn.w, hn[i][3]);
            ss[i][0] = fmaf(xv, ws.x, ss[i][0]);
            ss[i][1] = fmaf(xv, ws.y, ss[i][1]);
            ss[i][2] = fmaf(xv, ws.z, ss[i][2]);
            ss[i][3] = fmaf(xv, ws.w, ss[i][3]);
        }
    }

    float4 bb = *reinterpret_cast<const float4*>(&sb[g_c * 4]);
#pragma unroll
    for (int i = 0; i < 4; ++i) {
        int node = n0 + g_n * 4 + i;
        if (node < NN) {
            __half2 p0 = __floats2half2_rn(hn[i][0], hn[i][1]);
            __half2 p1 = __floats2half2_rn(hn[i][2], hn[i][3]);
            uint2 u = make_uint2(*reinterpret_cast<unsigned*>(&p0),
                                 *reinterpret_cast<unsigned*>(&p1));
            *(reinterpret_cast<uint2*>(g_HNh + (size_t)node * DIM) + g_c) = u;
            reinterpret_cast<float4*>(g_SB + (size_t)node * DIM)[g_c] =
                make_float4(ss[i][0] + bb.x, ss[i][1] + bb.y,
                            ss[i][2] + bb.z, ss[i][3] + bb.w);
        }
    }
}

// ---------------- bucket aggregation + relu (fp16 messages, fp32 accum) ----------
// one warp per node; lane = (edge_group:2, feature_quad:3).
// Each iteration consumes 4 edges; each lane loads 8 B (4 halves) of its quad.
// Inactive edge slots are redirected (branchless) to the permanent zero row
// g_HNh[NN]. fp16 rows halve the dominant L2 traffic term vs fp32.
__global__ void aggregate_relu_kernel(float* __restrict__ OUT, int zero_flag) {
    int node = (blockIdx.x * blockDim.x + threadIdx.x) >> 5;
    int lane = threadIdx.x & 31;
    if (node >= NN) return;

    int fq = (lane & 7) * 4;      // feature quad offset within the 32-dim row
    int eg = lane >> 3;           // edge group 0..3

    int cnt = g_cnt[node];
    int m = min(cnt, CAP);
    const int* bkt = &g_bucket[(size_t)node * CAP];
    // row = 8 uint2; this lane's quad is uint2 #(lane&7) of the row
    const uint2* hb = reinterpret_cast<const uint2*>(g_HNh) + (lane & 7);

    float4 acc = make_float4(0.f, 0.f, 0.f, 0.f);

    for (int base = 0; base < m; base += 32) {
        int nb = min(32, m - base);
        int idx = (lane < nb) ? bkt[base + lane] : NN;
        for (int j = 0; j < nb; j += 4) {
            int ej = j + eg;
            int s = __shfl_sync(0xffffffffu, idx, ej & 31);
            s = (ej < nb) ? s : NN;               // branchless: zero row
            uint2 u = hb[(size_t)s * 8];
            __half2 h0 = *reinterpret_cast<__half2*>(&u.x);
            __half2 h1 = *reinterpret_cast<__half2*>(&u.y);
            float2 f0 = __half22float2(h0);
            float2 f1 = __half22float2(h1);
            acc.x += f0.x; acc.y += f0.y; acc.z += f1.x; acc.w += f1.y;
        }
    }

    // reduce across the 4 edge groups (lanes l, l+8, l+16, l+24)
    acc.x += __shfl_xor_sync(0xffffffffu, acc.x, 8);
    acc.y += __shfl_xor_sync(0xffffffffu, acc.y, 8);
    acc.z += __shfl_xor_sync(0xffffffffu, acc.z, 8);
    acc.w += __shfl_xor_sync(0xffffffffu, acc.w, 8);
    acc.x += __shfl_xor_sync(0xffffffffu, acc.x, 16);
    acc.y += __shfl_xor_sync(0xffffffffu, acc.y, 16);
    acc.z += __shfl_xor_sync(0xffffffffu, acc.z, 16);
    acc.w += __shfl_xor_sync(0xffffffffu, acc.w, 16);

    if (eg == 0) {
        float4 sb = *reinterpret_cast<const float4*>(&g_SB[(size_t)node * DIM + fq]);
        float4 o;
        o.x = fmaxf(acc.x + sb.x, 0.f);
        o.y = fmaxf(acc.y + sb.y, 0.f);
        o.z = fmaxf(acc.z + sb.z, 0.f);
        o.w = fmaxf(acc.w + sb.w, 0.f);
        *reinterpret_cast<float4*>(&OUT[(size_t)node * DIM + fq]) = o;
        if (zero_flag && lane == 0) g_cnt[node] = 0;   // restore invariant
    }
}

// ---------------- final FC (H-part) + log_softmax ----------------
__global__ void fc_final_kernel(const float* __restrict__ W,   // full fc_w [224,10]
                                float* __restrict__ OUT) {
    __shared__ float sW[3 * DIM * NC];   // rows 128..223
    for (int i = threadIdx.x; i < 3 * DIM * NC; i += blockDim.x)
        sW[i] = W[FIN * NC + i];
    __syncthreads();

    int n = blockIdx.x * blockDim.x + threadIdx.x;
    if (n >= NN) return;

    float acc[NC];
    const float* p = g_fcp + (size_t)n * NC;
#pragma unroll
    for (int c = 0; c < NC; c++) acc[c] = p[c];

    const float* h1 = g_H1 + (size_t)n * DIM;
    const float* h2 = g_H2 + (size_t)n * DIM;
    const float* h3 = g_H3 + (size_t)n * DIM;
#pragma unroll 4
    for (int k = 0; k < DIM; ++k) {
        float v = h1[k];
        const float* w = &sW[k * NC];
#pragma unroll
        for (int c = 0; c < NC; c++) acc[c] = fmaf(v, w[c], acc[c]);
    }
#pragma unroll 4
    for (int k = 0; k < DIM; ++k) {
        float v = h2[k];
        const float* w = &sW[(DIM + k) * NC];
#pragma unroll
        for (int c = 0; c < NC; c++) acc[c] = fmaf(v, w[c], acc[c]);
    }
#pragma unroll 4
    for (int k = 0; k < DIM; ++k) {
        float v = h3[k];
        const float* w = &sW[(2 * DIM + k) * NC];
#pragma unroll
        for (int c = 0; c < NC; c++) acc[c] = fmaf(v, w[c], acc[c]);
    }

    float mx = acc[0];
#pragma unroll
    for (int c = 1; c < NC; c++) mx = fmaxf(mx, acc[c]);
    float s = 0.f;
#pragma unroll
    for (int c = 0; c < NC; c++) s += expf(acc[c] - mx);
    float l = logf(s);
    float* o = OUT + (size_t)n * NC;
#pragma unroll
    for (int c = 0; c < NC; c++) o[c] = acc[c] - mx - l;
}

// ---------------- launch ----------------
extern "C" void kernel_launch(void* const* d_in, const int* in_sizes, int n_in,
                              void* d_out, int out_size) {
    const float* x   = (const float*)d_in[0];
    const int*   src = (const int*)d_in[1];
    const int*   dst = (const int*)d_in[2];
    const float* Wn0 = (const float*)d_in[3];
    const float* bn0 = (const float*)d_in[4];
    const float* Ws0 = (const float*)d_in[5];
    const float* Wn1 = (const float*)d_in[6];
    const float* bn1 = (const float*)d_in[7];
    const float* Ws1 = (const float*)d_in[8];
    const float* Wn2 = (const float*)d_in[9];
    const float* bn2 = (const float*)d_in[10];
    const float* Ws2 = (const float*)d_in[11];
    const float* fcw = (const float*)d_in[12];
    const float* fcb = (const float*)d_in[13];
    float* out = (float*)d_out;

    float *H1, *H2, *H3;
    cudaGetSymbolAddress((void**)&H1, g_H1);
    cudaGetSymbolAddress((void**)&H2, g_H2);
    cudaGetSymbolAddress((void**)&H3, g_H3);

    constexpr int SMEMF = (128 * 33 + 2 * 128 * 32 + 32) * 4;   // 49792 B
    cudaFuncSetAttribute(fused0_kernel,
                         cudaFuncAttributeMaxDynamicSharedMemorySize, SMEMF);

    const int ablocks = (NN * 32 + 255) / 256;

    // layer 0 GEMM + edge scatter + partial FC, all overlapped in one launch
    fused0_kernel<<<2 * EVB, 256, SMEMF>>>(x, Wn0, bn0, Ws0, src, dst, fcw, fcb);
    aggregate_relu_kernel<<<ablocks, 256>>>(H1, 0);
    // layer 1
    gemm_dual32_kernel<<<GT, 256>>>(H1, Wn1, bn1, Ws1);
    aggregate_relu_kernel<<<ablocks, 256>>>(H2, 0);
    // layer 2
    gemm_dual32_kernel<<<GT, 256>>>(H2, Wn2, bn2, Ws2);
    aggregate_relu_kernel<<<ablocks, 256>>>(H3, 1);   // zeroes g_cnt after last use
    // readout (x-part already in g_fcp)
    fc_final_kernel<<<(NN + 255) / 256, 256>>>(fcw, out);
}